// round 6
// baseline (speedup 1.0000x reference)
#include <cuda_runtime.h>

#define N_NODES 100000
#define N_EDGES 1600000
#define IN_CH 128
#define HID 128
#define OUT_CH 64
#define NBLK ((N_NODES + 255) / 256)   // 391

// ---------------- scratch (static device globals; no allocation) ----------------
__device__ int   g_cnt[N_NODES];
__device__ int   g_rowptr[N_NODES + 1];
__device__ int   g_cursor[N_NODES];
__device__ int   g_colidx[N_EDGES];
__device__ float g_dinv[N_NODES];
__device__ int   g_blksum[NBLK];
__device__ int   g_blkoff[NBLK];
__device__ float g_xs1[N_NODES * HID];     // x @ W1 (unscaled -> independent of prep)
__device__ float g_xs2[N_NODES * OUT_CH];  // (h @ W2) * dinv[row]

// ---------------- f32x2 packed-FMA helpers ----------------
__device__ __forceinline__ unsigned long long ffma2(unsigned long long a,
                                                    unsigned long long b,
                                                    unsigned long long c) {
    unsigned long long d;
    asm("fma.rn.f32x2 %0, %1, %2, %3;" : "=l"(d) : "l"(a), "l"(b), "l"(c));
    return d;
}
__device__ __forceinline__ unsigned long long pack2(float x) {
    unsigned long long d;
    asm("mov.b64 %0, {%1, %1};" : "=l"(d) : "f"(x));
    return d;
}
__device__ __forceinline__ float2 unpack2(unsigned long long v) {
    float2 r;
    asm("mov.b64 {%0, %1}, %2;" : "=f"(r.x), "=f"(r.y) : "l"(v));
    return r;
}

// ---------------- degree histogram ----------------
__global__ void k_zero_cnt() {
    int i = blockIdx.x * blockDim.x + threadIdx.x;
    if (i < N_NODES) g_cnt[i] = 0;
}

__global__ void k_count(const int* __restrict__ ei) {
    int e = blockIdx.x * blockDim.x + threadIdx.x;
    if (e < N_EDGES) {
        int dst = ei[N_EDGES + e];
        atomicAdd(&g_cnt[dst], 1);
    }
}

// ---------------- coalesced 3-kernel scan ----------------
__global__ void __launch_bounds__(256) k_blocksum() {
    int i = blockIdx.x * 256 + threadIdx.x;
    int v = (i < N_NODES) ? g_cnt[i] : 0;
#pragma unroll
    for (int o = 16; o; o >>= 1) v += __shfl_down_sync(0xffffffffu, v, o);
    __shared__ int wsum[8];
    if ((threadIdx.x & 31) == 0) wsum[threadIdx.x >> 5] = v;
    __syncthreads();
    if (threadIdx.x < 8) {
        int s = wsum[threadIdx.x];
#pragma unroll
        for (int o = 4; o; o >>= 1) s += __shfl_down_sync(0xffu, s, o);
        if (threadIdx.x == 0) g_blksum[blockIdx.x] = s;
    }
}

__global__ void __launch_bounds__(512) k_scanblk() {
    __shared__ int sh[512];
    int t = threadIdx.x;
    int v = (t < NBLK) ? g_blksum[t] : 0;
    sh[t] = v;
    __syncthreads();
    for (int off = 1; off < 512; off <<= 1) {
        int u = (t >= off) ? sh[t - off] : 0;
        __syncthreads();
        sh[t] += u;
        __syncthreads();
    }
    if (t < NBLK) g_blkoff[t] = sh[t] - v;   // exclusive
    if (t == NBLK - 1) g_rowptr[N_NODES] = sh[t];
}

__global__ void __launch_bounds__(256) k_rowptr() {
    __shared__ int sh[256];
    int i = blockIdx.x * 256 + threadIdx.x;
    int c = (i < N_NODES) ? g_cnt[i] : 0;
    sh[threadIdx.x] = c;
    __syncthreads();
    for (int off = 1; off < 256; off <<= 1) {
        int u = (threadIdx.x >= off) ? sh[threadIdx.x - off] : 0;
        __syncthreads();
        sh[threadIdx.x] += u;
        __syncthreads();
    }
    if (i < N_NODES) {
        int excl = sh[threadIdx.x] - c + g_blkoff[blockIdx.x];
        g_rowptr[i] = excl;
        g_cursor[i] = excl;
        g_dinv[i] = rsqrtf((float)(c + 1));  // +1 self loop
    }
}

// ---------------- CSR fill ----------------
__global__ void k_scatter(const int* __restrict__ ei) {
    int e = blockIdx.x * blockDim.x + threadIdx.x;
    if (e < N_EDGES) {
        int src = ei[e];
        int dst = ei[N_EDGES + e];
        int pos = atomicAdd(&g_cursor[dst], 1);
        g_colidx[pos] = src;
    }
}

// ---------------- GEMM1: g_xs1 = x @ W1 (unscaled) ----------------
__global__ void __launch_bounds__(256) k_gemm1(const float* __restrict__ in,
                                               const float* __restrict__ W) {
    constexpr int NOUT = HID;
    constexpr int BM = 128, BK = 32, TM = 8, TN = NOUT / 16, TP = TN / 2;
    __shared__ __align__(16) float xs[BM][BK + 1];
    __shared__ __align__(16) float ws[BK][NOUT];

    int tid = threadIdx.x;
    int tcol = tid & 15;
    int trow = tid >> 4;
    int brow = blockIdx.x * BM;

    unsigned long long acc[TM][TP];
#pragma unroll
    for (int i = 0; i < TM; i++)
#pragma unroll
        for (int j = 0; j < TP; j++) acc[i][j] = 0ull;

    for (int k0 = 0; k0 < 128; k0 += BK) {
#pragma unroll
        for (int it = 0; it < BM * BK / (4 * 256); it++) {
            int idx = tid + it * 256;
            int r = idx >> 3;
            int kq = idx & 7;
            int row = brow + r;
            float4 v = make_float4(0.f, 0.f, 0.f, 0.f);
            if (row < N_NODES)
                v = *(const float4*)(in + row * 128 + k0 + kq * 4);
            xs[r][kq * 4 + 0] = v.x;
            xs[r][kq * 4 + 1] = v.y;
            xs[r][kq * 4 + 2] = v.z;
            xs[r][kq * 4 + 3] = v.w;
        }
#pragma unroll
        for (int it = 0; it < BK * NOUT / (4 * 256); it++) {
            int idx = tid + it * 256;
            int r = idx / (NOUT / 4);
            int cq = idx % (NOUT / 4);
            *(float4*)(&ws[r][cq * 4]) = *(const float4*)(W + (k0 + r) * NOUT + cq * 4);
        }
        __syncthreads();

#pragma unroll 4
        for (int kk = 0; kk < BK; kk++) {
            unsigned long long b[TP];
#pragma unroll
            for (int j = 0; j < TP; j += 2) {
                ulonglong2 bv = *(const ulonglong2*)(&ws[kk][tcol * TN + j * 2]);
                b[j] = bv.x;
                b[j + 1] = bv.y;
            }
#pragma unroll
            for (int i = 0; i < TM; i++) {
                unsigned long long pa = pack2(xs[trow * TM + i][kk]);
#pragma unroll
                for (int j = 0; j < TP; j++) acc[i][j] = ffma2(pa, b[j], acc[i][j]);
            }
        }
        __syncthreads();
    }

#pragma unroll
    for (int i = 0; i < TM; i++) {
        int row = brow + trow * TM + i;
        if (row < N_NODES) {
            float r[TN];
#pragma unroll
            for (int j = 0; j < TP; j++) {
                float2 u = unpack2(acc[i][j]);
                r[j * 2] = u.x;
                r[j * 2 + 1] = u.y;
            }
#pragma unroll
            for (int j = 0; j < TN; j += 4)
                *(float4*)(g_xs1 + row * NOUT + tcol * TN + j) =
                    make_float4(r[j], r[j + 1], r[j + 2], r[j + 3]);
        }
    }
}

// ---------------- fused agg1 + gemm2 ----------------
// per warp: h = l2norm(relu(dinv[v]*(sum dinv[src]*xs1[src] + dinv[v]*xs1[v]) + b1))
// then xs2[v] = (h @ W2) * dinv[v]   (GEMV, W2 staged in smem)
// grid: exactly N_NODES/8 blocks of 8 warps (100000 % 8 == 0)
__global__ void __launch_bounds__(256) k_agg1_gemv(const float* __restrict__ b1,
                                                   const float* __restrict__ W2) {
    __shared__ __align__(16) float w2s[128][OUT_CH];  // 32 KB
    __shared__ float hs[8][HID];                      // 4 KB

    int tid = threadIdx.x;
    // cooperative W2 load: 8192 floats / 256 threads = 8 float4 each
#pragma unroll
    for (int it = 0; it < 8; it++) {
        int idx = (tid + it * 256) * 4;
        *(float4*)(&w2s[idx / OUT_CH][idx % OUT_CH]) = *(const float4*)(W2 + idx);
    }
    __syncthreads();

    int w = tid >> 5;
    int lane = tid & 31;
    int v = blockIdx.x * 8 + w;   // always < N_NODES

    const float4* xrow = (const float4*)g_xs1;
    float dvv = g_dinv[v];
    float4 self = xrow[v * 32 + lane];
    float4 acc;
    acc.x = self.x * dvv; acc.y = self.y * dvv;
    acc.z = self.z * dvv; acc.w = self.w * dvv;

    int beg = g_rowptr[v];
    int end = g_rowptr[v + 1];
    for (int e = beg; e < end; e += 32) {
        int m = end - e;
        int c = 0;
        float dv = 0.f;
        if (lane < m) {
            c = g_colidx[e + lane];
            dv = g_dinv[c];
        }
        if (m >= 32) {
#pragma unroll
            for (int j = 0; j < 32; j++) {
                int col = __shfl_sync(0xffffffffu, c, j);
                float d = __shfl_sync(0xffffffffu, dv, j);
                float4 val = xrow[col * 32 + lane];
                acc.x = fmaf(val.x, d, acc.x);
                acc.y = fmaf(val.y, d, acc.y);
                acc.z = fmaf(val.z, d, acc.z);
                acc.w = fmaf(val.w, d, acc.w);
            }
        } else {
            for (int j = 0; j < m; j++) {
                int col = __shfl_sync(0xffffffffu, c, j);
                float d = __shfl_sync(0xffffffffu, dv, j);
                float4 val = xrow[col * 32 + lane];
                acc.x = fmaf(val.x, d, acc.x);
                acc.y = fmaf(val.y, d, acc.y);
                acc.z = fmaf(val.z, d, acc.z);
                acc.w = fmaf(val.w, d, acc.w);
            }
        }
    }

    float4 bb = ((const float4*)b1)[lane];
    float4 h;
    h.x = fmaxf(fmaf(dvv, acc.x, bb.x), 0.f);
    h.y = fmaxf(fmaf(dvv, acc.y, bb.y), 0.f);
    h.z = fmaxf(fmaf(dvv, acc.z, bb.z), 0.f);
    h.w = fmaxf(fmaf(dvv, acc.w, bb.w), 0.f);

    float ss = h.x * h.x + h.y * h.y + h.z * h.z + h.w * h.w;
#pragma unroll
    for (int off = 16; off; off >>= 1) ss += __shfl_xor_sync(0xffffffffu, ss, off);
    float sc = 1.0f / fmaxf(sqrtf(ss), 1e-12f);
    h.x *= sc; h.y *= sc; h.z *= sc; h.w *= sc;

    // stage h for warp-local GEMV
    *(float4*)(&hs[w][lane * 4]) = h;
    __syncwarp();

    // GEMV: lane computes output cols 2*lane, 2*lane+1
    unsigned long long a2 = 0ull;
#pragma unroll 16
    for (int k = 0; k < 128; k++) {
        unsigned long long wv = *(const unsigned long long*)(&w2s[k][lane * 2]);
        a2 = ffma2(pack2(hs[w][k]), wv, a2);
    }
    float2 r = unpack2(a2);
    r.x *= dvv;
    r.y *= dvv;
    *(float2*)(g_xs2 + v * OUT_CH + lane * 2) = r;
}

// ---------------- aggregation layer 2: warp per node, 64 feats ----------------
__global__ void __launch_bounds__(256) k_agg2(const float* __restrict__ b2,
                                              float* __restrict__ out) {
    int gw = (blockIdx.x * blockDim.x + threadIdx.x) >> 5;
    int lane = threadIdx.x & 31;
    if (gw >= N_NODES) return;
    int v = gw;

    const float2* xrow = (const float2*)g_xs2;
    float2 acc = xrow[v * 32 + lane];  // self term

    int beg = g_rowptr[v];
    int end = g_rowptr[v + 1];
    for (int e = beg; e < end; e += 32) {
        int m = end - e;
        int c = (lane < m) ? g_colidx[e + lane] : 0;
        if (m >= 32) {
#pragma unroll
            for (int j = 0; j < 32; j++) {
                int col = __shfl_sync(0xffffffffu, c, j);
                float2 val = xrow[col * 32 + lane];
                acc.x += val.x; acc.y += val.y;
            }
        } else {
            for (int j = 0; j < m; j++) {
                int col = __shfl_sync(0xffffffffu, c, j);
                float2 val = xrow[col * 32 + lane];
                acc.x += val.x; acc.y += val.y;
            }
        }
    }

    float di = g_dinv[v];
    float2 bb = ((const float2*)b2)[lane];
    float2 o;
    o.x = fmaf(di, acc.x, bb.x);
    o.y = fmaf(di, acc.y, bb.y);
    ((float2*)out)[v * 32 + lane] = o;
}

// ---------------- launch (prep chain forked onto a side stream) ----------------
static cudaStream_t s_side = nullptr;
static cudaEvent_t e_fork = nullptr, e_join = nullptr;

extern "C" void kernel_launch(void* const* d_in, const int* in_sizes, int n_in,
                              void* d_out, int out_size) {
    const float* x  = (const float*)d_in[0];
    const int*   ei = (const int*)d_in[1];   // JAX default: int64 request -> int32
    const float* W1 = (const float*)d_in[2];
    const float* b1 = (const float*)d_in[3];
    const float* W2 = (const float*)d_in[4];
    const float* b2 = (const float*)d_in[5];
    float* out = (float*)d_out;

    if (!s_side) {  // first call is the uncaptured correctness run
        cudaStreamCreateWithFlags(&s_side, cudaStreamNonBlocking);
        cudaEventCreateWithFlags(&e_fork, cudaEventDisableTiming);
        cudaEventCreateWithFlags(&e_join, cudaEventDisableTiming);
    }

    // fork: CSR/degree prep on side stream, gemm1 on main stream
    cudaEventRecord(e_fork, 0);
    cudaStreamWaitEvent(s_side, e_fork, 0);

    k_zero_cnt<<<(N_NODES + 255) / 256, 256, 0, s_side>>>();
    k_count<<<(N_EDGES + 255) / 256, 256, 0, s_side>>>(ei);
    k_blocksum<<<NBLK, 256, 0, s_side>>>();
    k_scanblk<<<1, 512, 0, s_side>>>();
    k_rowptr<<<NBLK, 256, 0, s_side>>>();
    k_scatter<<<(N_EDGES + 255) / 256, 256, 0, s_side>>>(ei);
    cudaEventRecord(e_join, s_side);

    k_gemm1<<<(N_NODES + 127) / 128, 256>>>(x, W1);

    // join: everything below needs both gemm1 and the CSR
    cudaStreamWaitEvent(0, e_join, 0);

    k_agg1_gemv<<<N_NODES / 8, 256>>>(b1, W2);
    k_agg2<<<(N_NODES * 32 + 255) / 256, 256>>>(b2, out);
}

// round 7
// speedup vs baseline: 1.1171x; 1.1171x over previous
#include <cuda_runtime.h>

#define N_NODES 100000
#define N_EDGES 1600000
#define IN_CH 128
#define HID 128
#define OUT_CH 64
#define NBLK ((N_NODES + 255) / 256)   // 391
#define NCHUNK 4
#define CHUNK (N_NODES / NCHUNK)       // 25000

// ---------------- scratch (static device globals; no allocation) ----------------
__device__ int   g_cnt[N_NODES];
__device__ int   g_rowptr[N_NODES + 1];
__device__ int   g_cursor[N_NODES];
__device__ int   g_colidx[N_EDGES];
__device__ float g_dinv[N_NODES];
__device__ int   g_blksum[NBLK];
__device__ int   g_blkoff[NBLK];
__device__ float g_xs1[N_NODES * HID];     // x @ W1 (unscaled -> independent of prep)
__device__ float g_h  [N_NODES * HID];     // layer-1 activations (relu + l2norm)
__device__ float g_xs2[N_NODES * OUT_CH];  // (h @ W2) * dinv[row]

// ---------------- f32x2 packed-FMA helpers ----------------
__device__ __forceinline__ unsigned long long ffma2(unsigned long long a,
                                                    unsigned long long b,
                                                    unsigned long long c) {
    unsigned long long d;
    asm("fma.rn.f32x2 %0, %1, %2, %3;" : "=l"(d) : "l"(a), "l"(b), "l"(c));
    return d;
}
__device__ __forceinline__ unsigned long long pack2(float x) {
    unsigned long long d;
    asm("mov.b64 %0, {%1, %1};" : "=l"(d) : "f"(x));
    return d;
}
__device__ __forceinline__ float2 unpack2(unsigned long long v) {
    float2 r;
    asm("mov.b64 {%0, %1}, %2;" : "=f"(r.x), "=f"(r.y) : "l"(v));
    return r;
}

// ---------------- degree histogram ----------------
__global__ void k_zero_cnt() {
    int i = blockIdx.x * blockDim.x + threadIdx.x;
    if (i < N_NODES) g_cnt[i] = 0;
}

__global__ void k_count(const int* __restrict__ ei) {
    int e = blockIdx.x * blockDim.x + threadIdx.x;
    if (e < N_EDGES) {
        int dst = ei[N_EDGES + e];
        atomicAdd(&g_cnt[dst], 1);
    }
}

// ---------------- coalesced 3-kernel scan ----------------
__global__ void __launch_bounds__(256) k_blocksum() {
    int i = blockIdx.x * 256 + threadIdx.x;
    int v = (i < N_NODES) ? g_cnt[i] : 0;
#pragma unroll
    for (int o = 16; o; o >>= 1) v += __shfl_down_sync(0xffffffffu, v, o);
    __shared__ int wsum[8];
    if ((threadIdx.x & 31) == 0) wsum[threadIdx.x >> 5] = v;
    __syncthreads();
    if (threadIdx.x < 8) {
        int s = wsum[threadIdx.x];
#pragma unroll
        for (int o = 4; o; o >>= 1) s += __shfl_down_sync(0xffu, s, o);
        if (threadIdx.x == 0) g_blksum[blockIdx.x] = s;
    }
}

__global__ void __launch_bounds__(512) k_scanblk() {
    __shared__ int sh[512];
    int t = threadIdx.x;
    int v = (t < NBLK) ? g_blksum[t] : 0;
    sh[t] = v;
    __syncthreads();
    for (int off = 1; off < 512; off <<= 1) {
        int u = (t >= off) ? sh[t - off] : 0;
        __syncthreads();
        sh[t] += u;
        __syncthreads();
    }
    if (t < NBLK) g_blkoff[t] = sh[t] - v;   // exclusive
    if (t == NBLK - 1) g_rowptr[N_NODES] = sh[t];
}

__global__ void __launch_bounds__(256) k_rowptr() {
    __shared__ int sh[256];
    int i = blockIdx.x * 256 + threadIdx.x;
    int c = (i < N_NODES) ? g_cnt[i] : 0;
    sh[threadIdx.x] = c;
    __syncthreads();
    for (int off = 1; off < 256; off <<= 1) {
        int u = (threadIdx.x >= off) ? sh[threadIdx.x - off] : 0;
        __syncthreads();
        sh[threadIdx.x] += u;
        __syncthreads();
    }
    if (i < N_NODES) {
        int excl = sh[threadIdx.x] - c + g_blkoff[blockIdx.x];
        g_rowptr[i] = excl;
        g_cursor[i] = excl;
        g_dinv[i] = rsqrtf((float)(c + 1));  // +1 self loop
    }
}

// ---------------- CSR fill ----------------
__global__ void k_scatter(const int* __restrict__ ei) {
    int e = blockIdx.x * blockDim.x + threadIdx.x;
    if (e < N_EDGES) {
        int src = ei[e];
        int dst = ei[N_EDGES + e];
        int pos = atomicAdd(&g_cursor[dst], 1);
        g_colidx[pos] = src;
    }
}

// ---------------- GEMM: out[row0..row1) = (in @ W) * (scale ? dinv : 1) ------
template <int NOUT, bool SCALE>
__device__ __forceinline__ void gemm_body(const float* __restrict__ in,
                                          const float* __restrict__ W,
                                          float* __restrict__ out,
                                          int row0, int row1) {
    constexpr int BM = 128, BK = 32, TM = 8, TN = NOUT / 16, TP = TN / 2;
    __shared__ __align__(16) float xs[BM][BK + 1];
    __shared__ __align__(16) float ws[BK][NOUT];

    int tid = threadIdx.x;
    int tcol = tid & 15;
    int trow = tid >> 4;
    int brow = row0 + blockIdx.x * BM;

    unsigned long long acc[TM][TP];
#pragma unroll
    for (int i = 0; i < TM; i++)
#pragma unroll
        for (int j = 0; j < TP; j++) acc[i][j] = 0ull;

    for (int k0 = 0; k0 < 128; k0 += BK) {
#pragma unroll
        for (int it = 0; it < BM * BK / (4 * 256); it++) {
            int idx = tid + it * 256;
            int r = idx >> 3;
            int kq = idx & 7;
            int row = brow + r;
            float4 v = make_float4(0.f, 0.f, 0.f, 0.f);
            if (row < row1)
                v = *(const float4*)(in + row * 128 + k0 + kq * 4);
            xs[r][kq * 4 + 0] = v.x;
            xs[r][kq * 4 + 1] = v.y;
            xs[r][kq * 4 + 2] = v.z;
            xs[r][kq * 4 + 3] = v.w;
        }
#pragma unroll
        for (int it = 0; it < BK * NOUT / (4 * 256); it++) {
            int idx = tid + it * 256;
            int r = idx / (NOUT / 4);
            int cq = idx % (NOUT / 4);
            *(float4*)(&ws[r][cq * 4]) = *(const float4*)(W + (k0 + r) * NOUT + cq * 4);
        }
        __syncthreads();

#pragma unroll 4
        for (int kk = 0; kk < BK; kk++) {
            unsigned long long b[TP];
#pragma unroll
            for (int j = 0; j < TP; j += 2) {
                ulonglong2 bv = *(const ulonglong2*)(&ws[kk][tcol * TN + j * 2]);
                b[j] = bv.x;
                b[j + 1] = bv.y;
            }
#pragma unroll
            for (int i = 0; i < TM; i++) {
                unsigned long long pa = pack2(xs[trow * TM + i][kk]);
#pragma unroll
                for (int j = 0; j < TP; j++) acc[i][j] = ffma2(pa, b[j], acc[i][j]);
            }
        }
        __syncthreads();
    }

#pragma unroll
    for (int i = 0; i < TM; i++) {
        int row = brow + trow * TM + i;
        if (row < row1) {
            float di = SCALE ? g_dinv[row] : 1.0f;
            float r[TN];
#pragma unroll
            for (int j = 0; j < TP; j++) {
                float2 u = unpack2(acc[i][j]);
                r[j * 2] = u.x * di;
                r[j * 2 + 1] = u.y * di;
            }
#pragma unroll
            for (int j = 0; j < TN; j += 4)
                *(float4*)(out + row * NOUT + tcol * TN + j) =
                    make_float4(r[j], r[j + 1], r[j + 2], r[j + 3]);
        }
    }
}

__global__ void __launch_bounds__(256) k_gemm1(const float* __restrict__ x,
                                               const float* __restrict__ W1) {
    gemm_body<HID, false>(x, W1, g_xs1, 0, N_NODES);
}
__global__ void __launch_bounds__(256) k_gemm2(const float* __restrict__ W2,
                                               int row0, int row1) {
    gemm_body<OUT_CH, true>(g_h, W2, g_xs2, row0, row1);
}

// ---------------- aggregation layer 1 (node range): warp per node ---------------
__global__ void __launch_bounds__(256) k_agg1(const float* __restrict__ b1, int v0) {
    int gw = (blockIdx.x * blockDim.x + threadIdx.x) >> 5;
    int lane = threadIdx.x & 31;
    int v = v0 + gw;                   // chunk size divisible by 8 -> no stragglers
    if (v >= N_NODES) return;

    const float4* xrow = (const float4*)g_xs1;
    float dvv = g_dinv[v];
    float4 self = xrow[v * 32 + lane];
    float4 acc;
    acc.x = self.x * dvv; acc.y = self.y * dvv;
    acc.z = self.z * dvv; acc.w = self.w * dvv;

    int beg = g_rowptr[v];
    int end = g_rowptr[v + 1];
    for (int e = beg; e < end; e += 32) {
        int m = end - e;
        int c = 0;
        float dv = 0.f;
        if (lane < m) {
            c = g_colidx[e + lane];
            dv = g_dinv[c];
        }
        if (m >= 32) {
#pragma unroll
            for (int j = 0; j < 32; j++) {
                int col = __shfl_sync(0xffffffffu, c, j);
                float d = __shfl_sync(0xffffffffu, dv, j);
                float4 val = xrow[col * 32 + lane];
                acc.x = fmaf(val.x, d, acc.x);
                acc.y = fmaf(val.y, d, acc.y);
                acc.z = fmaf(val.z, d, acc.z);
                acc.w = fmaf(val.w, d, acc.w);
            }
        } else {
            for (int j = 0; j < m; j++) {
                int col = __shfl_sync(0xffffffffu, c, j);
                float d = __shfl_sync(0xffffffffu, dv, j);
                float4 val = xrow[col * 32 + lane];
                acc.x = fmaf(val.x, d, acc.x);
                acc.y = fmaf(val.y, d, acc.y);
                acc.z = fmaf(val.z, d, acc.z);
                acc.w = fmaf(val.w, d, acc.w);
            }
        }
    }

    float4 bb = ((const float4*)b1)[lane];
    float4 h;
    h.x = fmaxf(fmaf(dvv, acc.x, bb.x), 0.f);
    h.y = fmaxf(fmaf(dvv, acc.y, bb.y), 0.f);
    h.z = fmaxf(fmaf(dvv, acc.z, bb.z), 0.f);
    h.w = fmaxf(fmaf(dvv, acc.w, bb.w), 0.f);

    float ss = h.x * h.x + h.y * h.y + h.z * h.z + h.w * h.w;
#pragma unroll
    for (int off = 16; off; off >>= 1) ss += __shfl_xor_sync(0xffffffffu, ss, off);
    float sc = 1.0f / fmaxf(sqrtf(ss), 1e-12f);
    h.x *= sc; h.y *= sc; h.z *= sc; h.w *= sc;

    ((float4*)g_h)[v * 32 + lane] = h;
}

// ---------------- aggregation layer 2: warp per node, 64 feats ----------------
__global__ void __launch_bounds__(256) k_agg2(const float* __restrict__ b2,
                                              float* __restrict__ out) {
    int gw = (blockIdx.x * blockDim.x + threadIdx.x) >> 5;
    int lane = threadIdx.x & 31;
    if (gw >= N_NODES) return;
    int v = gw;

    const float2* xrow = (const float2*)g_xs2;
    float2 acc = xrow[v * 32 + lane];  // self term

    int beg = g_rowptr[v];
    int end = g_rowptr[v + 1];
    for (int e = beg; e < end; e += 32) {
        int m = end - e;
        int c = (lane < m) ? g_colidx[e + lane] : 0;
        if (m >= 32) {
#pragma unroll
            for (int j = 0; j < 32; j++) {
                int col = __shfl_sync(0xffffffffu, c, j);
                float2 val = xrow[col * 32 + lane];
                acc.x += val.x; acc.y += val.y;
            }
        } else {
            for (int j = 0; j < m; j++) {
                int col = __shfl_sync(0xffffffffu, c, j);
                float2 val = xrow[col * 32 + lane];
                acc.x += val.x; acc.y += val.y;
            }
        }
    }

    float di = g_dinv[v];
    float2 bb = ((const float2*)b2)[lane];
    float2 o;
    o.x = fmaf(di, acc.x, bb.x);
    o.y = fmaf(di, acc.y, bb.y);
    ((float2*)out)[v * 32 + lane] = o;
}

// ---------------- launch: prep ∥ gemm1, then pipelined agg1→gemm2 -------------
static cudaStream_t s_side = nullptr;
static cudaEvent_t e_fork = nullptr, e_join = nullptr, e_g2 = nullptr;
static cudaEvent_t e_chunk[NCHUNK] = {nullptr, nullptr, nullptr, nullptr};

extern "C" void kernel_launch(void* const* d_in, const int* in_sizes, int n_in,
                              void* d_out, int out_size) {
    const float* x  = (const float*)d_in[0];
    const int*   ei = (const int*)d_in[1];   // JAX default: int64 request -> int32
    const float* W1 = (const float*)d_in[2];
    const float* b1 = (const float*)d_in[3];
    const float* W2 = (const float*)d_in[4];
    const float* b2 = (const float*)d_in[5];
    float* out = (float*)d_out;

    if (!s_side) {  // first call is the uncaptured correctness run
        cudaStreamCreateWithFlags(&s_side, cudaStreamNonBlocking);
        cudaEventCreateWithFlags(&e_fork, cudaEventDisableTiming);
        cudaEventCreateWithFlags(&e_join, cudaEventDisableTiming);
        cudaEventCreateWithFlags(&e_g2, cudaEventDisableTiming);
        for (int i = 0; i < NCHUNK; i++)
            cudaEventCreateWithFlags(&e_chunk[i], cudaEventDisableTiming);
    }

    // fork: CSR/degree prep on side stream, gemm1 on main stream
    cudaEventRecord(e_fork, 0);
    cudaStreamWaitEvent(s_side, e_fork, 0);

    k_zero_cnt<<<(N_NODES + 255) / 256, 256, 0, s_side>>>();
    k_count<<<(N_EDGES + 255) / 256, 256, 0, s_side>>>(ei);
    k_blocksum<<<NBLK, 256, 0, s_side>>>();
    k_scanblk<<<1, 512, 0, s_side>>>();
    k_rowptr<<<NBLK, 256, 0, s_side>>>();
    k_scatter<<<(N_EDGES + 255) / 256, 256, 0, s_side>>>(ei);
    cudaEventRecord(e_join, s_side);

    k_gemm1<<<(N_NODES + 127) / 128, 256>>>(x, W1);

    // join: agg1 needs both gemm1 (main) and CSR (side)
    cudaStreamWaitEvent(0, e_join, 0);

    // pipelined agg1 chunks (main) -> gemm2 chunks (side)
    for (int i = 0; i < NCHUNK; i++) {
        int v0 = i * CHUNK;
        k_agg1<<<CHUNK * 32 / 256, 256>>>(b1, v0);
        cudaEventRecord(e_chunk[i], 0);
        cudaStreamWaitEvent(s_side, e_chunk[i], 0);
        k_gemm2<<<(CHUNK + 127) / 128, 256, 0, s_side>>>(W2, v0, v0 + CHUNK);
    }
    cudaEventRecord(e_g2, s_side);
    cudaStreamWaitEvent(0, e_g2, 0);

    k_agg2<<<(N_NODES * 32 + 255) / 256, 256>>>(b2, out);
}

// round 8
// speedup vs baseline: 1.1696x; 1.0470x over previous
#include <cuda_runtime.h>

#define N_NODES 100000
#define N_EDGES 1600000
#define IN_CH 128
#define HID 128
#define OUT_CH 64
#define MAXDEG 64

// ---------------- scratch (static device globals; no allocation) ----------------
__device__ int   g_cnt[N_NODES];
__device__ int   g_ell[N_NODES * MAXDEG];     // ELL adjacency (by dst)
__device__ float g_coef[N_NODES * MAXDEG];    // dinv[src] per ELL slot
__device__ float g_dinv[N_NODES];
__device__ float g_xs1[N_NODES * HID];        // x @ W1 (unscaled)
__device__ float g_h  [N_NODES * HID];        // layer-1 activations
__device__ float g_xs2[N_NODES * OUT_CH];     // (h @ W2) * dinv[row]

// ---------------- f32x2 packed-FMA helpers ----------------
__device__ __forceinline__ unsigned long long ffma2(unsigned long long a,
                                                    unsigned long long b,
                                                    unsigned long long c) {
    unsigned long long d;
    asm("fma.rn.f32x2 %0, %1, %2, %3;" : "=l"(d) : "l"(a), "l"(b), "l"(c));
    return d;
}
__device__ __forceinline__ unsigned long long pack2(float x) {
    unsigned long long d;
    asm("mov.b64 %0, {%1, %1};" : "=l"(d) : "f"(x));
    return d;
}
__device__ __forceinline__ float2 unpack2(unsigned long long v) {
    float2 r;
    asm("mov.b64 {%0, %1}, %2;" : "=f"(r.x), "=f"(r.y) : "l"(v));
    return r;
}

// ---------------- prep: ELL build ----------------
__global__ void k_zero_cnt() {
    int i = blockIdx.x * blockDim.x + threadIdx.x;
    if (i < N_NODES) g_cnt[i] = 0;
}

__global__ void k_scatter_ell(const int* __restrict__ ei) {
    int e = blockIdx.x * blockDim.x + threadIdx.x;
    if (e < N_EDGES) {
        int src = ei[e];
        int dst = ei[N_EDGES + e];
        int slot = atomicAdd(&g_cnt[dst], 1);
        g_ell[dst * MAXDEG + slot] = src;
    }
}

__global__ void k_dinv() {
    int i = blockIdx.x * blockDim.x + threadIdx.x;
    if (i < N_NODES) g_dinv[i] = rsqrtf((float)(g_cnt[i] + 1));  // +1 self loop
}

// coef[slot] = dinv[src] (coalesced read of ell, gather dinv, coalesced write)
__global__ void k_coef() {
    int idx = blockIdx.x * blockDim.x + threadIdx.x;  // over N_NODES*MAXDEG
    int v = idx >> 6;
    int s = idx & (MAXDEG - 1);
    if (v < N_NODES && s < g_cnt[v])
        g_coef[idx] = g_dinv[g_ell[idx]];
}

// ---------------- GEMM: out = (in @ W) * (scale ? dinv : 1) ----------------
template <int NOUT, bool SCALE>
__device__ __forceinline__ void gemm_body(const float* __restrict__ in,
                                          const float* __restrict__ W,
                                          float* __restrict__ out) {
    constexpr int BM = 128, BK = 32, TM = 8, TN = NOUT / 16, TP = TN / 2;
    __shared__ __align__(16) float xs[BM][BK + 1];
    __shared__ __align__(16) float ws[BK][NOUT];

    int tid = threadIdx.x;
    int tcol = tid & 15;
    int trow = tid >> 4;
    int brow = blockIdx.x * BM;

    unsigned long long acc[TM][TP];
#pragma unroll
    for (int i = 0; i < TM; i++)
#pragma unroll
        for (int j = 0; j < TP; j++) acc[i][j] = 0ull;

    for (int k0 = 0; k0 < 128; k0 += BK) {
#pragma unroll
        for (int it = 0; it < BM * BK / (4 * 256); it++) {
            int idx = tid + it * 256;
            int r = idx >> 3;
            int kq = idx & 7;
            int row = brow + r;
            float4 v = make_float4(0.f, 0.f, 0.f, 0.f);
            if (row < N_NODES)
                v = *(const float4*)(in + row * 128 + k0 + kq * 4);
            xs[r][kq * 4 + 0] = v.x;
            xs[r][kq * 4 + 1] = v.y;
            xs[r][kq * 4 + 2] = v.z;
            xs[r][kq * 4 + 3] = v.w;
        }
#pragma unroll
        for (int it = 0; it < BK * NOUT / (4 * 256); it++) {
            int idx = tid + it * 256;
            int r = idx / (NOUT / 4);
            int cq = idx % (NOUT / 4);
            *(float4*)(&ws[r][cq * 4]) = *(const float4*)(W + (k0 + r) * NOUT + cq * 4);
        }
        __syncthreads();

#pragma unroll 4
        for (int kk = 0; kk < BK; kk++) {
            unsigned long long b[TP];
#pragma unroll
            for (int j = 0; j < TP; j += 2) {
                ulonglong2 bv = *(const ulonglong2*)(&ws[kk][tcol * TN + j * 2]);
                b[j] = bv.x;
                b[j + 1] = bv.y;
            }
#pragma unroll
            for (int i = 0; i < TM; i++) {
                unsigned long long pa = pack2(xs[trow * TM + i][kk]);
#pragma unroll
                for (int j = 0; j < TP; j++) acc[i][j] = ffma2(pa, b[j], acc[i][j]);
            }
        }
        __syncthreads();
    }

#pragma unroll
    for (int i = 0; i < TM; i++) {
        int row = brow + trow * TM + i;
        if (row < N_NODES) {
            float di = SCALE ? g_dinv[row] : 1.0f;
            float r[TN];
#pragma unroll
            for (int j = 0; j < TP; j++) {
                float2 u = unpack2(acc[i][j]);
                r[j * 2] = u.x * di;
                r[j * 2 + 1] = u.y * di;
            }
#pragma unroll
            for (int j = 0; j < TN; j += 4)
                *(float4*)(out + row * NOUT + tcol * TN + j) =
                    make_float4(r[j], r[j + 1], r[j + 2], r[j + 3]);
        }
    }
}

__global__ void __launch_bounds__(256) k_gemm1(const float* __restrict__ x,
                                               const float* __restrict__ W1) {
    gemm_body<HID, false>(x, W1, g_xs1);
}
__global__ void __launch_bounds__(256) k_gemm2(const float* __restrict__ W2) {
    gemm_body<OUT_CH, true>(g_h, W2, g_xs2);
}

// ---------------- aggregation layer 1: warp per node, 128 feats ----------------
// h[v] = l2norm(relu(dinv[v]*(sum coef[e]*xs1[src] + dinv[v]*xs1[v]) + b1))
__global__ void __launch_bounds__(256) k_agg1(const float* __restrict__ b1) {
    int gw = (blockIdx.x * blockDim.x + threadIdx.x) >> 5;
    int lane = threadIdx.x & 31;
    if (gw >= N_NODES) return;
    int v = gw;

    const float4* xrow = (const float4*)g_xs1;
    float dvv = g_dinv[v];
    float4 self = xrow[v * 32 + lane];
    float4 acc;
    acc.x = self.x * dvv; acc.y = self.y * dvv;
    acc.z = self.z * dvv; acc.w = self.w * dvv;

    int deg = g_cnt[v];
    int base = v * MAXDEG;
    for (int e = 0; e < deg; e += 32) {
        int m = deg - e;
        int c = 0;
        float dv = 0.f;
        if (lane < m) {
            c = g_ell[base + e + lane];
            dv = g_coef[base + e + lane];
        }
        if (m >= 32) {
#pragma unroll
            for (int j = 0; j < 32; j++) {
                int col = __shfl_sync(0xffffffffu, c, j);
                float d = __shfl_sync(0xffffffffu, dv, j);
                float4 val = xrow[col * 32 + lane];
                acc.x = fmaf(val.x, d, acc.x);
                acc.y = fmaf(val.y, d, acc.y);
                acc.z = fmaf(val.z, d, acc.z);
                acc.w = fmaf(val.w, d, acc.w);
            }
        } else {
            for (int j = 0; j < m; j++) {
                int col = __shfl_sync(0xffffffffu, c, j);
                float d = __shfl_sync(0xffffffffu, dv, j);
                float4 val = xrow[col * 32 + lane];
                acc.x = fmaf(val.x, d, acc.x);
                acc.y = fmaf(val.y, d, acc.y);
                acc.z = fmaf(val.z, d, acc.z);
                acc.w = fmaf(val.w, d, acc.w);
            }
        }
    }

    float4 bb = ((const float4*)b1)[lane];
    float4 h;
    h.x = fmaxf(fmaf(dvv, acc.x, bb.x), 0.f);
    h.y = fmaxf(fmaf(dvv, acc.y, bb.y), 0.f);
    h.z = fmaxf(fmaf(dvv, acc.z, bb.z), 0.f);
    h.w = fmaxf(fmaf(dvv, acc.w, bb.w), 0.f);

    float ss = h.x * h.x + h.y * h.y + h.z * h.z + h.w * h.w;
#pragma unroll
    for (int off = 16; off; off >>= 1) ss += __shfl_xor_sync(0xffffffffu, ss, off);
    float sc = 1.0f / fmaxf(sqrtf(ss), 1e-12f);
    h.x *= sc; h.y *= sc; h.z *= sc; h.w *= sc;

    ((float4*)g_h)[v * 32 + lane] = h;
}

// ---------------- aggregation layer 2: warp per node, 64 feats ----------------
// out[v] = dinv[v]*(sum xs2[src] + xs2[v]) + b2   (dinv[src] folded in gemm2)
__global__ void __launch_bounds__(256) k_agg2(const float* __restrict__ b2,
                                              float* __restrict__ out) {
    int gw = (blockIdx.x * blockDim.x + threadIdx.x) >> 5;
    int lane = threadIdx.x & 31;
    if (gw >= N_NODES) return;
    int v = gw;

    const float2* xrow = (const float2*)g_xs2;
    float2 acc = xrow[v * 32 + lane];  // self term

    int deg = g_cnt[v];
    int base = v * MAXDEG;
    for (int e = 0; e < deg; e += 32) {
        int m = deg - e;
        int c = (lane < m) ? g_ell[base + e + lane] : 0;
        if (m >= 32) {
#pragma unroll
            for (int j = 0; j < 32; j++) {
                int col = __shfl_sync(0xffffffffu, c, j);
                float2 val = xrow[col * 32 + lane];
                acc.x += val.x; acc.y += val.y;
            }
        } else {
            for (int j = 0; j < m; j++) {
                int col = __shfl_sync(0xffffffffu, c, j);
                float2 val = xrow[col * 32 + lane];
                acc.x += val.x; acc.y += val.y;
            }
        }
    }

    float di = g_dinv[v];
    float2 bb = ((const float2*)b2)[lane];
    float2 o;
    o.x = fmaf(di, acc.x, bb.x);
    o.y = fmaf(di, acc.y, bb.y);
    ((float2*)out)[v * 32 + lane] = o;
}

// ---------------- launch (prep chain forked onto a side stream) ----------------
static cudaStream_t s_side = nullptr;
static cudaEvent_t e_fork = nullptr, e_join = nullptr;

extern "C" void kernel_launch(void* const* d_in, const int* in_sizes, int n_in,
                              void* d_out, int out_size) {
    const float* x  = (const float*)d_in[0];
    const int*   ei = (const int*)d_in[1];   // JAX default: int64 request -> int32
    const float* W1 = (const float*)d_in[2];
    const float* b1 = (const float*)d_in[3];
    const float* W2 = (const float*)d_in[4];
    const float* b2 = (const float*)d_in[5];
    float* out = (float*)d_out;

    if (!s_side) {  // first call is the uncaptured correctness run
        cudaStreamCreateWithFlags(&s_side, cudaStreamNonBlocking);
        cudaEventCreateWithFlags(&e_fork, cudaEventDisableTiming);
        cudaEventCreateWithFlags(&e_join, cudaEventDisableTiming);
    }

    // fork: ELL prep on side stream, gemm1 on main stream
    cudaEventRecord(e_fork, 0);
    cudaStreamWaitEvent(s_side, e_fork, 0);

    k_zero_cnt<<<(N_NODES + 255) / 256, 256, 0, s_side>>>();
    k_scatter_ell<<<(N_EDGES + 255) / 256, 256, 0, s_side>>>(ei);
    k_dinv<<<(N_NODES + 255) / 256, 256, 0, s_side>>>();
    k_coef<<<(N_NODES * MAXDEG + 255) / 256, 256, 0, s_side>>>();
    cudaEventRecord(e_join, s_side);

    k_gemm1<<<(N_NODES + 127) / 128, 256>>>(x, W1);

    // join: everything below needs both gemm1 and the ELL/dinv
    cudaStreamWaitEvent(0, e_join, 0);

    k_agg1<<<(N_NODES * 32 + 255) / 256, 256>>>(b1);
    k_gemm2<<<(N_NODES + 127) / 128, 256>>>(W2);
    k_agg2<<<(N_NODES * 32 + 255) / 256, 256>>>(b2, out);
}

// round 9
// speedup vs baseline: 1.2001x; 1.0261x over previous
#include <cuda_runtime.h>

#define N_NODES 100000
#define N_EDGES 1600000
#define IN_CH 128
#define HID 128
#define OUT_CH 64
#define MAXDEG 64

// ---------------- scratch (static device globals; no allocation) ----------------
__device__ int   g_cnt[N_NODES];
__device__ int   g_ell[N_NODES * MAXDEG];     // ELL adjacency (by dst)
__device__ float g_dinv[N_NODES];
__device__ float g_xs1[N_NODES * HID];        // x @ W1 (unscaled)
__device__ float g_h  [N_NODES * HID];        // layer-1 activations
__device__ float g_xs2[N_NODES * OUT_CH];     // (h @ W2) * dinv[row]

// ---------------- f32x2 packed-FMA helpers ----------------
__device__ __forceinline__ unsigned long long ffma2(unsigned long long a,
                                                    unsigned long long b,
                                                    unsigned long long c) {
    unsigned long long d;
    asm("fma.rn.f32x2 %0, %1, %2, %3;" : "=l"(d) : "l"(a), "l"(b), "l"(c));
    return d;
}
__device__ __forceinline__ unsigned long long pack2(float x) {
    unsigned long long d;
    asm("mov.b64 %0, {%1, %1};" : "=l"(d) : "f"(x));
    return d;
}
__device__ __forceinline__ float2 unpack2(unsigned long long v) {
    float2 r;
    asm("mov.b64 {%0, %1}, %2;" : "=f"(r.x), "=f"(r.y) : "l"(v));
    return r;
}

// ---------------- prep: ELL build ----------------
__global__ void k_zero_cnt() {
    int i = blockIdx.x * blockDim.x + threadIdx.x;
    if (i < N_NODES) g_cnt[i] = 0;
}

__global__ void k_scatter_ell(const int* __restrict__ ei) {
    int e = blockIdx.x * blockDim.x + threadIdx.x;
    if (e < N_EDGES) {
        int src = ei[e];
        int dst = ei[N_EDGES + e];
        int slot = atomicAdd(&g_cnt[dst], 1);
        g_ell[dst * MAXDEG + slot] = src;
    }
}

__global__ void k_dinv() {
    int i = blockIdx.x * blockDim.x + threadIdx.x;
    if (i < N_NODES) g_dinv[i] = rsqrtf((float)(g_cnt[i] + 1));  // +1 self loop
}

// ---------------- GEMM: out = (in @ W) * (scale ? dinv : 1) ----------------
template <int NOUT, bool SCALE>
__device__ __forceinline__ void gemm_body(const float* __restrict__ in,
                                          const float* __restrict__ W,
                                          float* __restrict__ out) {
    constexpr int BM = 128, BK = 32, TM = 8, TN = NOUT / 16, TP = TN / 2;
    __shared__ __align__(16) float xs[BM][BK + 1];
    __shared__ __align__(16) float ws[BK][NOUT];

    int tid = threadIdx.x;
    int tcol = tid & 15;
    int trow = tid >> 4;
    int brow = blockIdx.x * BM;

    unsigned long long acc[TM][TP];
#pragma unroll
    for (int i = 0; i < TM; i++)
#pragma unroll
        for (int j = 0; j < TP; j++) acc[i][j] = 0ull;

    for (int k0 = 0; k0 < 128; k0 += BK) {
#pragma unroll
        for (int it = 0; it < BM * BK / (4 * 256); it++) {
            int idx = tid + it * 256;
            int r = idx >> 3;
            int kq = idx & 7;
            int row = brow + r;
            float4 v = make_float4(0.f, 0.f, 0.f, 0.f);
            if (row < N_NODES)
                v = *(const float4*)(in + row * 128 + k0 + kq * 4);
            xs[r][kq * 4 + 0] = v.x;
            xs[r][kq * 4 + 1] = v.y;
            xs[r][kq * 4 + 2] = v.z;
            xs[r][kq * 4 + 3] = v.w;
        }
#pragma unroll
        for (int it = 0; it < BK * NOUT / (4 * 256); it++) {
            int idx = tid + it * 256;
            int r = idx / (NOUT / 4);
            int cq = idx % (NOUT / 4);
            *(float4*)(&ws[r][cq * 4]) = *(const float4*)(W + (k0 + r) * NOUT + cq * 4);
        }
        __syncthreads();

#pragma unroll 4
        for (int kk = 0; kk < BK; kk++) {
            unsigned long long b[TP];
#pragma unroll
            for (int j = 0; j < TP; j += 2) {
                ulonglong2 bv = *(const ulonglong2*)(&ws[kk][tcol * TN + j * 2]);
                b[j] = bv.x;
                b[j + 1] = bv.y;
            }
#pragma unroll
            for (int i = 0; i < TM; i++) {
                unsigned long long pa = pack2(xs[trow * TM + i][kk]);
#pragma unroll
                for (int j = 0; j < TP; j++) acc[i][j] = ffma2(pa, b[j], acc[i][j]);
            }
        }
        __syncthreads();
    }

#pragma unroll
    for (int i = 0; i < TM; i++) {
        int row = brow + trow * TM + i;
        if (row < N_NODES) {
            float di = SCALE ? g_dinv[row] : 1.0f;
            float r[TN];
#pragma unroll
            for (int j = 0; j < TP; j++) {
                float2 u = unpack2(acc[i][j]);
                r[j * 2] = u.x * di;
                r[j * 2 + 1] = u.y * di;
            }
#pragma unroll
            for (int j = 0; j < TN; j += 4)
                *(float4*)(out + row * NOUT + tcol * TN + j) =
                    make_float4(r[j], r[j + 1], r[j + 2], r[j + 3]);
        }
    }
}

__global__ void __launch_bounds__(256) k_gemm1(const float* __restrict__ x,
                                               const float* __restrict__ W1) {
    gemm_body<HID, false>(x, W1, g_xs1);
}
__global__ void __launch_bounds__(256) k_gemm2(const float* __restrict__ W2) {
    gemm_body<OUT_CH, true>(g_h, W2, g_xs2);
}

// ---------------- aggregation layer 1: warp per node, 128 feats ----------------
// h[v] = l2norm(relu(dinv[v]*(sum dinv[src]*xs1[src] + dinv[v]*xs1[v]) + b1))
__global__ void __launch_bounds__(256) k_agg1(const float* __restrict__ b1) {
    int gw = (blockIdx.x * blockDim.x + threadIdx.x) >> 5;
    int lane = threadIdx.x & 31;
    if (gw >= N_NODES) return;
    int v = gw;

    const float4* xrow = (const float4*)g_xs1;
    float dvv = g_dinv[v];
    float4 self = xrow[v * 32 + lane];
    float4 acc;
    acc.x = self.x * dvv; acc.y = self.y * dvv;
    acc.z = self.z * dvv; acc.w = self.w * dvv;

    int deg = g_cnt[v];
    int base = v * MAXDEG;
    for (int e = 0; e < deg; e += 32) {
        int m = deg - e;
        int c = 0;
        float dv = 0.f;
        if (lane < m) {
            c = g_ell[base + e + lane];
            dv = g_dinv[c];
        }
        if (m >= 32) {
#pragma unroll
            for (int j = 0; j < 32; j++) {
                int col = __shfl_sync(0xffffffffu, c, j);
                float d = __shfl_sync(0xffffffffu, dv, j);
                float4 val = xrow[col * 32 + lane];
                acc.x = fmaf(val.x, d, acc.x);
                acc.y = fmaf(val.y, d, acc.y);
                acc.z = fmaf(val.z, d, acc.z);
                acc.w = fmaf(val.w, d, acc.w);
            }
        } else {
            for (int j = 0; j < m; j++) {
                int col = __shfl_sync(0xffffffffu, c, j);
                float d = __shfl_sync(0xffffffffu, dv, j);
                float4 val = xrow[col * 32 + lane];
                acc.x = fmaf(val.x, d, acc.x);
                acc.y = fmaf(val.y, d, acc.y);
                acc.z = fmaf(val.z, d, acc.z);
                acc.w = fmaf(val.w, d, acc.w);
            }
        }
    }

    float4 bb = ((const float4*)b1)[lane];
    float4 h;
    h.x = fmaxf(fmaf(dvv, acc.x, bb.x), 0.f);
    h.y = fmaxf(fmaf(dvv, acc.y, bb.y), 0.f);
    h.z = fmaxf(fmaf(dvv, acc.z, bb.z), 0.f);
    h.w = fmaxf(fmaf(dvv, acc.w, bb.w), 0.f);

    float ss = h.x * h.x + h.y * h.y + h.z * h.z + h.w * h.w;
#pragma unroll
    for (int off = 16; off; off >>= 1) ss += __shfl_xor_sync(0xffffffffu, ss, off);
    float sc = 1.0f / fmaxf(sqrtf(ss), 1e-12f);
    h.x *= sc; h.y *= sc; h.z *= sc; h.w *= sc;

    ((float4*)g_h)[v * 32 + lane] = h;
}

// ---------------- aggregation layer 2: warp per node, 64 feats ----------------
// out[v] = dinv[v]*(sum xs2[src] + xs2[v]) + b2   (dinv[src] folded in gemm2)
__global__ void __launch_bounds__(256) k_agg2(const float* __restrict__ b2,
                                              float* __restrict__ out) {
    int gw = (blockIdx.x * blockDim.x + threadIdx.x) >> 5;
    int lane = threadIdx.x & 31;
    if (gw >= N_NODES) return;
    int v = gw;

    const float2* xrow = (const float2*)g_xs2;
    float2 acc = xrow[v * 32 + lane];  // self term

    int deg = g_cnt[v];
    int base = v * MAXDEG;
    for (int e = 0; e < deg; e += 32) {
        int m = deg - e;
        int c = (lane < m) ? g_ell[base + e + lane] : 0;
        if (m >= 32) {
#pragma unroll
            for (int j = 0; j < 32; j++) {
                int col = __shfl_sync(0xffffffffu, c, j);
                float2 val = xrow[col * 32 + lane];
                acc.x += val.x; acc.y += val.y;
            }
        } else {
            for (int j = 0; j < m; j++) {
                int col = __shfl_sync(0xffffffffu, c, j);
                float2 val = xrow[col * 32 + lane];
                acc.x += val.x; acc.y += val.y;
            }
        }
    }

    float di = g_dinv[v];
    float2 bb = ((const float2*)b2)[lane];
    float2 o;
    o.x = fmaf(di, acc.x, bb.x);
    o.y = fmaf(di, acc.y, bb.y);
    ((float2*)out)[v * 32 + lane] = o;
}

// ---------------- launch (prep chain forked onto a side stream) ----------------
static cudaStream_t s_side = nullptr;
static cudaEvent_t e_fork = nullptr, e_join = nullptr;

extern "C" void kernel_launch(void* const* d_in, const int* in_sizes, int n_in,
                              void* d_out, int out_size) {
    const float* x  = (const float*)d_in[0];
    const int*   ei = (const int*)d_in[1];   // JAX default: int64 request -> int32
    const float* W1 = (const float*)d_in[2];
    const float* b1 = (const float*)d_in[3];
    const float* W2 = (const float*)d_in[4];
    const float* b2 = (const float*)d_in[5];
    float* out = (float*)d_out;

    if (!s_side) {  // first call is the uncaptured correctness run
        cudaStreamCreateWithFlags(&s_side, cudaStreamNonBlocking);
        cudaEventCreateWithFlags(&e_fork, cudaEventDisableTiming);
        cudaEventCreateWithFlags(&e_join, cudaEventDisableTiming);
    }

    // fork: ELL prep on side stream, gemm1 on main stream
    cudaEventRecord(e_fork, 0);
    cudaStreamWaitEvent(s_side, e_fork, 0);

    k_zero_cnt<<<(N_NODES + 255) / 256, 256, 0, s_side>>>();
    k_scatter_ell<<<(N_EDGES + 255) / 256, 256, 0, s_side>>>(ei);
    k_dinv<<<(N_NODES + 255) / 256, 256, 0, s_side>>>();
    cudaEventRecord(e_join, s_side);

    k_gemm1<<<(N_NODES + 127) / 128, 256>>>(x, W1);

    // join: everything below needs both gemm1 and the ELL/dinv
    cudaStreamWaitEvent(0, e_join, 0);

    k_agg1<<<(N_NODES * 32 + 255) / 256, 256>>>(b1);
    k_gemm2<<<(N_NODES + 127) / 128, 256>>>(W2);
    k_agg2<<<(N_NODES * 32 + 255) / 256, 256>>>(b2, out);
}

// round 10
// speedup vs baseline: 1.2473x; 1.0393x over previous
#include <cuda_runtime.h>

#define N_NODES 100000
#define N_EDGES 1600000
#define IN_CH 128
#define HID 128
#define OUT_CH 64
#define MAXDEG 64

// ---------------- scratch (static device globals; no allocation) ----------------
__device__ int   g_cnt[N_NODES];
__device__ int   g_ell[N_NODES * MAXDEG];     // ELL adjacency (by dst)
__device__ float g_dinv[N_NODES];
__device__ float g_xs1[N_NODES * HID];        // x @ W1 (unscaled)
__device__ float g_h  [N_NODES * HID];        // layer-1 activations
__device__ float g_xs2[N_NODES * OUT_CH];     // (h @ W2) * dinv[row]

// ---------------- f32x2 packed-FMA helpers ----------------
__device__ __forceinline__ unsigned long long ffma2(unsigned long long a,
                                                    unsigned long long b,
                                                    unsigned long long c) {
    unsigned long long d;
    asm("fma.rn.f32x2 %0, %1, %2, %3;" : "=l"(d) : "l"(a), "l"(b), "l"(c));
    return d;
}
__device__ __forceinline__ unsigned long long pack2(float x) {
    unsigned long long d;
    asm("mov.b64 %0, {%1, %1};" : "=l"(d) : "f"(x));
    return d;
}
__device__ __forceinline__ float2 unpack2(unsigned long long v) {
    float2 r;
    asm("mov.b64 {%0, %1}, %2;" : "=f"(r.x), "=f"(r.y) : "l"(v));
    return r;
}

// ---------------- prep: ELL build ----------------
__global__ void k_zero_cnt() {
    int i = blockIdx.x * blockDim.x + threadIdx.x;
    if (i < N_NODES) g_cnt[i] = 0;
}

__global__ void k_scatter_ell(const int* __restrict__ ei) {
    int e = blockIdx.x * blockDim.x + threadIdx.x;
    if (e < N_EDGES) {
        int src = ei[e];
        int dst = ei[N_EDGES + e];
        int slot = atomicAdd(&g_cnt[dst], 1);
        g_ell[dst * MAXDEG + slot] = src;
    }
}

__global__ void k_dinv() {
    int i = blockIdx.x * blockDim.x + threadIdx.x;
    if (i < N_NODES) g_dinv[i] = rsqrtf((float)(g_cnt[i] + 1));  // +1 self loop
}

// ---------------- GEMM: out = (in @ W) * (scale ? dinv : 1) ----------------
// x tile stored TRANSPOSED in smem: xt[k][row] -> a-operand loads are 2x LDS.128
// (broadcast, 1 wavefront each) instead of 8 scalar LDS (16 wavefronts).
template <int NOUT, bool SCALE>
__device__ __forceinline__ void gemm_body(const float* __restrict__ in,
                                          const float* __restrict__ W,
                                          float* __restrict__ out) {
    constexpr int BM = 128, BK = 32, TM = 8, TN = NOUT / 16, TP = TN / 2;
    __shared__ __align__(16) float xt[BK][BM + 4];   // transposed x tile
    __shared__ __align__(16) float ws[BK][NOUT];

    int tid = threadIdx.x;
    int tcol = tid & 15;
    int trow = tid >> 4;
    int brow = blockIdx.x * BM;

    unsigned long long acc[TM][TP];
#pragma unroll
    for (int i = 0; i < TM; i++)
#pragma unroll
        for (int j = 0; j < TP; j++) acc[i][j] = 0ull;

    for (int k0 = 0; k0 < 128; k0 += BK) {
        // x tile: 128 rows x 32 k, stored transposed
#pragma unroll
        for (int it = 0; it < BM * BK / (4 * 256); it++) {
            int idx = tid + it * 256;
            int r = idx >> 3;      // row 0..127
            int kq = idx & 7;      // k-quad 0..7
            int row = brow + r;
            float4 v = make_float4(0.f, 0.f, 0.f, 0.f);
            if (row < N_NODES)
                v = *(const float4*)(in + row * 128 + k0 + kq * 4);
            xt[kq * 4 + 0][r] = v.x;
            xt[kq * 4 + 1][r] = v.y;
            xt[kq * 4 + 2][r] = v.z;
            xt[kq * 4 + 3][r] = v.w;
        }
        // W tile: 32 x NOUT
#pragma unroll
        for (int it = 0; it < BK * NOUT / (4 * 256); it++) {
            int idx = tid + it * 256;
            int r = idx / (NOUT / 4);
            int cq = idx % (NOUT / 4);
            *(float4*)(&ws[r][cq * 4]) = *(const float4*)(W + (k0 + r) * NOUT + cq * 4);
        }
        __syncthreads();

#pragma unroll 4
        for (int kk = 0; kk < BK; kk++) {
            // a: 8 row values, vectorized (broadcast within half-warp)
            float4 a0 = *(const float4*)(&xt[kk][trow * TM]);
            float4 a1 = *(const float4*)(&xt[kk][trow * TM + 4]);
            unsigned long long pa[TM];
            pa[0] = pack2(a0.x); pa[1] = pack2(a0.y);
            pa[2] = pack2(a0.z); pa[3] = pack2(a0.w);
            pa[4] = pack2(a1.x); pa[5] = pack2(a1.y);
            pa[6] = pack2(a1.z); pa[7] = pack2(a1.w);

            unsigned long long b[TP];
#pragma unroll
            for (int j = 0; j < TP; j += 2) {
                ulonglong2 bv = *(const ulonglong2*)(&ws[kk][tcol * TN + j * 2]);
                b[j] = bv.x;
                b[j + 1] = bv.y;
            }
#pragma unroll
            for (int i = 0; i < TM; i++)
#pragma unroll
                for (int j = 0; j < TP; j++) acc[i][j] = ffma2(pa[i], b[j], acc[i][j]);
        }
        __syncthreads();
    }

#pragma unroll
    for (int i = 0; i < TM; i++) {
        int row = brow + trow * TM + i;
        if (row < N_NODES) {
            float di = SCALE ? g_dinv[row] : 1.0f;
            float r[TN];
#pragma unroll
            for (int j = 0; j < TP; j++) {
                float2 u = unpack2(acc[i][j]);
                r[j * 2] = u.x * di;
                r[j * 2 + 1] = u.y * di;
            }
#pragma unroll
            for (int j = 0; j < TN; j += 4)
                *(float4*)(out + row * NOUT + tcol * TN + j) =
                    make_float4(r[j], r[j + 1], r[j + 2], r[j + 3]);
        }
    }
}

__global__ void __launch_bounds__(256) k_gemm1(const float* __restrict__ x,
                                               const float* __restrict__ W1) {
    gemm_body<HID, false>(x, W1, g_xs1);
}
__global__ void __launch_bounds__(256) k_gemm2(const float* __restrict__ W2) {
    gemm_body<OUT_CH, true>(g_h, W2, g_xs2);
}

// ---------------- aggregation layer 1: warp per node, 128 feats ----------------
// h[v] = l2norm(relu(dinv[v]*(sum dinv[src]*xs1[src] + dinv[v]*xs1[v]) + b1))
__global__ void __launch_bounds__(256) k_agg1(const float* __restrict__ b1) {
    int gw = (blockIdx.x * blockDim.x + threadIdx.x) >> 5;
    int lane = threadIdx.x & 31;
    if (gw >= N_NODES) return;
    int v = gw;

    const float4* xrow = (const float4*)g_xs1;
    float dvv = g_dinv[v];
    float4 self = xrow[v * 32 + lane];
    float4 acc;
    acc.x = self.x * dvv; acc.y = self.y * dvv;
    acc.z = self.z * dvv; acc.w = self.w * dvv;

    int deg = g_cnt[v];
    int base = v * MAXDEG;
    for (int e = 0; e < deg; e += 32) {
        int m = deg - e;
        int c = 0;
        float dv = 0.f;
        if (lane < m) {
            c = g_ell[base + e + lane];
            dv = g_dinv[c];
        }
        if (m >= 32) {
#pragma unroll
            for (int j = 0; j < 32; j++) {
                int col = __shfl_sync(0xffffffffu, c, j);
                float d = __shfl_sync(0xffffffffu, dv, j);
                float4 val = xrow[col * 32 + lane];
                acc.x = fmaf(val.x, d, acc.x);
                acc.y = fmaf(val.y, d, acc.y);
                acc.z = fmaf(val.z, d, acc.z);
                acc.w = fmaf(val.w, d, acc.w);
            }
        } else {
            for (int j = 0; j < m; j++) {
                int col = __shfl_sync(0xffffffffu, c, j);
                float d = __shfl_sync(0xffffffffu, dv, j);
                float4 val = xrow[col * 32 + lane];
                acc.x = fmaf(val.x, d, acc.x);
                acc.y = fmaf(val.y, d, acc.y);
                acc.z = fmaf(val.z, d, acc.z);
                acc.w = fmaf(val.w, d, acc.w);
            }
        }
    }

    float4 bb = ((const float4*)b1)[lane];
    float4 h;
    h.x = fmaxf(fmaf(dvv, acc.x, bb.x), 0.f);
    h.y = fmaxf(fmaf(dvv, acc.y, bb.y), 0.f);
    h.z = fmaxf(fmaf(dvv, acc.z, bb.z), 0.f);
    h.w = fmaxf(fmaf(dvv, acc.w, bb.w), 0.f);

    float ss = h.x * h.x + h.y * h.y + h.z * h.z + h.w * h.w;
#pragma unroll
    for (int off = 16; off; off >>= 1) ss += __shfl_xor_sync(0xffffffffu, ss, off);
    float sc = 1.0f / fmaxf(sqrtf(ss), 1e-12f);
    h.x *= sc; h.y *= sc; h.z *= sc; h.w *= sc;

    ((float4*)g_h)[v * 32 + lane] = h;
}

// ---------------- aggregation layer 2: warp per node, 64 feats ----------------
// out[v] = dinv[v]*(sum xs2[src] + xs2[v]) + b2   (dinv[src] folded in gemm2)
__global__ void __launch_bounds__(256) k_agg2(const float* __restrict__ b2,
                                              float* __restrict__ out) {
    int gw = (blockIdx.x * blockDim.x + threadIdx.x) >> 5;
    int lane = threadIdx.x & 31;
    if (gw >= N_NODES) return;
    int v = gw;

    const float2* xrow = (const float2*)g_xs2;
    float2 acc = xrow[v * 32 + lane];  // self term

    int deg = g_cnt[v];
    int base = v * MAXDEG;
    for (int e = 0; e < deg; e += 32) {
        int m = deg - e;
        int c = (lane < m) ? g_ell[base + e + lane] : 0;
        if (m >= 32) {
#pragma unroll
            for (int j = 0; j < 32; j++) {
                int col = __shfl_sync(0xffffffffu, c, j);
                float2 val = xrow[col * 32 + lane];
                acc.x += val.x; acc.y += val.y;
            }
        } else {
            for (int j = 0; j < m; j++) {
                int col = __shfl_sync(0xffffffffu, c, j);
                float2 val = xrow[col * 32 + lane];
                acc.x += val.x; acc.y += val.y;
            }
        }
    }

    float di = g_dinv[v];
    float2 bb = ((const float2*)b2)[lane];
    float2 o;
    o.x = fmaf(di, acc.x, bb.x);
    o.y = fmaf(di, acc.y, bb.y);
    ((float2*)out)[v * 32 + lane] = o;
}

// ---------------- launch (prep chain forked onto a side stream) ----------------
static cudaStream_t s_side = nullptr;
static cudaEvent_t e_fork = nullptr, e_join = nullptr;

extern "C" void kernel_launch(void* const* d_in, const int* in_sizes, int n_in,
                              void* d_out, int out_size) {
    const float* x  = (const float*)d_in[0];
    const int*   ei = (const int*)d_in[1];   // JAX default: int64 request -> int32
    const float* W1 = (const float*)d_in[2];
    const float* b1 = (const float*)d_in[3];
    const float* W2 = (const float*)d_in[4];
    const float* b2 = (const float*)d_in[5];
    float* out = (float*)d_out;

    if (!s_side) {  // first call is the uncaptured correctness run
        cudaStreamCreateWithFlags(&s_side, cudaStreamNonBlocking);
        cudaEventCreateWithFlags(&e_fork, cudaEventDisableTiming);
        cudaEventCreateWithFlags(&e_join, cudaEventDisableTiming);
    }

    // fork: ELL prep on side stream, gemm1 on main stream
    cudaEventRecord(e_fork, 0);
    cudaStreamWaitEvent(s_side, e_fork, 0);

    k_zero_cnt<<<(N_NODES + 255) / 256, 256, 0, s_side>>>();
    k_scatter_ell<<<(N_EDGES + 255) / 256, 256, 0, s_side>>>(ei);
    k_dinv<<<(N_NODES + 255) / 256, 256, 0, s_side>>>();
    cudaEventRecord(e_join, s_side);

    k_gemm1<<<(N_NODES + 127) / 128, 256>>>(x, W1);

    // join: everything below needs both gemm1 and the ELL/dinv
    cudaStreamWaitEvent(0, e_join, 0);

    k_agg1<<<(N_NODES * 32 + 255) / 256, 256>>>(b1);
    k_gemm2<<<(N_NODES + 127) / 128, 256>>>(W2);
    k_agg2<<<(N_NODES * 32 + 255) / 256, 256>>>(b2, out);
}